// round 3
// baseline (speedup 1.0000x reference)
#include <cuda_runtime.h>
#include <cuda_bf16.h>
#include <cstdint>
#include <cstddef>

#define Bn   64
#define Tn   1024
#define Dn   512
#define Hn   256
#define Gn   1024     /* 4*H */
#define NTOT 2048     /* both directions */
#define Mrows (Bn * Tn)
#define EPSC 0.001f

// ---------------- scratch (static device globals; allocation-free) ----------------
__device__ float          g_xg[(size_t)Bn * Tn * NTOT];   // 512 MB  xg for both dirs
__device__ __nv_bfloat16  g_ahi[(size_t)Mrows * Dn];      // 64 MB
__device__ __nv_bfloat16  g_alo[(size_t)Mrows * Dn];      // 64 MB
__device__ __nv_bfloat16  g_wthi[(size_t)NTOT * Dn];      // 2 MB  W^T hi  [n][k]
__device__ __nv_bfloat16  g_wtlo[(size_t)NTOT * Dn];      // 2 MB  W^T lo
__device__ float          g_bias2[NTOT];
__device__ float          g_hbuf[2][2][Bn * Hn];          // [parity][dir][b*H+j]
__device__ int            g_len[Bn];
__device__ unsigned       g_flags[128];                   // [dir*64 + bs*8 + hs]

__device__ __forceinline__ float sigf(float x)  { return 1.0f / (1.0f + __expf(-x)); }
__device__ __forceinline__ float tanhf_(float x){ return 2.0f / (1.0f + __expf(-2.0f * x)) - 1.0f; }

__device__ __forceinline__ uint32_t smem_u32(const void* p) {
    uint32_t a;
    asm("{ .reg .u64 t; cvta.to.shared.u64 t, %1; cvt.u32.u64 %0, t; }" : "=r"(a) : "l"(p));
    return a;
}
__device__ __forceinline__ void cp16(uint32_t dst, const void* src) {
    asm volatile("cp.async.cg.shared.global [%0], [%1], 16;" :: "r"(dst), "l"(src));
}
#define CP_COMMIT() asm volatile("cp.async.commit_group;" ::: "memory")
#define CP_WAIT1()  asm volatile("cp.async.wait_group 1;" ::: "memory")
#define CP_WAIT0()  asm volatile("cp.async.wait_group 0;" ::: "memory")

__device__ __forceinline__ void ldsm4(uint32_t& r0, uint32_t& r1, uint32_t& r2, uint32_t& r3,
                                      uint32_t addr) {
    asm volatile("ldmatrix.sync.aligned.m8n8.x4.shared.b16 {%0,%1,%2,%3}, [%4];"
                 : "=r"(r0), "=r"(r1), "=r"(r2), "=r"(r3) : "r"(addr));
}
__device__ __forceinline__ void mma16816(float* c, const uint32_t* a, uint32_t b0, uint32_t b1) {
    asm volatile("mma.sync.aligned.m16n8k16.row.col.f32.bf16.bf16.f32 "
                 "{%0,%1,%2,%3}, {%4,%5,%6,%7}, {%8,%9}, {%0,%1,%2,%3};"
                 : "+f"(c[0]), "+f"(c[1]), "+f"(c[2]), "+f"(c[3])
                 : "r"(a[0]), "r"(a[1]), "r"(a[2]), "r"(a[3]), "r"(b0), "r"(b1));
}

// ---------------- init -------------------------------------------------------------
__global__ void init_kernel() {
    if (threadIdx.x < 128) g_flags[threadIdx.x] = 0u;
}

// ---------------- lengths ----------------------------------------------------------
__global__ void lengths_kernel(const float* __restrict__ pads) {
    __shared__ float red[256];
    const int b = blockIdx.x;
    float s = 0.f;
    for (int t = threadIdx.x; t < Tn; t += 256) s += pads[b * Tn + t];
    red[threadIdx.x] = s;
    __syncthreads();
    for (int o = 128; o > 0; o >>= 1) {
        if (threadIdx.x < o) red[threadIdx.x] += red[threadIdx.x + o];
        __syncthreads();
    }
    if (threadIdx.x == 0) g_len[b] = Tn - (int)(red[0] + 0.5f);
}

// ---------------- BN + mask + bf16 hi/lo split -------------------------------------
__global__ void bn_split_kernel(const float* __restrict__ in, const float* __restrict__ pads,
                                const float* __restrict__ scale, const float* __restrict__ bias,
                                const float* __restrict__ mean, const float* __restrict__ var) {
    const int row = blockIdx.x;
    const int d   = threadIdx.x * 4;
    const float keep = 1.0f - pads[row];
    float4 v  = *(const float4*)(in + (size_t)row * Dn + d);
    float4 sc = *(const float4*)(scale + d);
    float4 bi = *(const float4*)(bias + d);
    float4 mu = *(const float4*)(mean + d);
    float4 va = *(const float4*)(var + d);
    float o[4];
    o[0] = ((v.x - mu.x) * ((1.0f + sc.x) * rsqrtf(va.x + EPSC)) + bi.x) * keep;
    o[1] = ((v.y - mu.y) * ((1.0f + sc.y) * rsqrtf(va.y + EPSC)) + bi.y) * keep;
    o[2] = ((v.z - mu.z) * ((1.0f + sc.z) * rsqrtf(va.z + EPSC)) + bi.z) * keep;
    o[3] = ((v.w - mu.w) * ((1.0f + sc.w) * rsqrtf(va.w + EPSC)) + bi.w) * keep;
    __nv_bfloat16 hi[4], lo[4];
#pragma unroll
    for (int q = 0; q < 4; q++) {
        hi[q] = __float2bfloat16(o[q]);
        lo[q] = __float2bfloat16(o[q] - __bfloat162float(hi[q]));
    }
    *(__nv_bfloat162*)(g_ahi + (size_t)row * Dn + d)     = {hi[0], hi[1]};
    *(__nv_bfloat162*)(g_ahi + (size_t)row * Dn + d + 2) = {hi[2], hi[3]};
    *(__nv_bfloat162*)(g_alo + (size_t)row * Dn + d)     = {lo[0], lo[1]};
    *(__nv_bfloat162*)(g_alo + (size_t)row * Dn + d + 2) = {lo[2], lo[3]};
}

// ---------------- W transpose + split + bias concat --------------------------------
__global__ void wprep_kernel(const float* __restrict__ Wxf, const float* __restrict__ Wxb,
                             const float* __restrict__ bf, const float* __restrict__ bb) {
    const int n = blockIdx.x;                 // 0..2047
    const float* W = (n < Gn) ? Wxf : Wxb;
    const int nl = n & (Gn - 1);
    for (int k = threadIdx.x; k < Dn; k += 128) {
        float v = W[(size_t)k * Gn + nl];
        __nv_bfloat16 h = __float2bfloat16(v);
        g_wthi[(size_t)n * Dn + k] = h;
        g_wtlo[(size_t)n * Dn + k] = __float2bfloat16(v - __bfloat162float(h));
    }
    if (threadIdx.x == 0) g_bias2[n] = (n < Gn) ? bf[nl] : bb[nl];
}

// ---------------- mma.sync GEMM: g_xg[65536,2048] = A_split @ W_split^T + bias -----
// CTA tile M=128, N=128, BK=64 bf16 (128 B/row, SW128-swizzled), double-buffered.
// 24 chunks: region 0 = A_hi*W_hi, 1 = A_lo*W_hi, 2 = A_hi*W_lo.
#define GCHUNKS 24
#define GSTAGE 32768                 /* (128 + 128) rows * 128 B */
#define GSMEM  (2 * GSTAGE)

__global__ void __launch_bounds__(256, 2) gemm_mma_kernel() {
    extern __shared__ __align__(1024) char sm[];
    const uint32_t smb = smem_u32(sm);
    // stage s: A at smb + s*GSTAGE, B at +16384
    const int tid  = threadIdx.x;
    const int wid  = tid >> 5, lane = tid & 31;
    const int n0   = blockIdx.x * 128;
    const int m0   = blockIdx.y * 128;
    const int wm   = wid & 3;        // 4 m-subtiles of 32
    const int wn   = wid >> 2;       // 2 n-subtiles of 64

    // per-thread cp.async (row, chunk) assignments: 1024 items per operand, 4/thread
    // item = tid + j*256 -> row = item>>3, ci = item&7
    // smem offset: row*128 + (ci*16 ^ ((row&7)<<4))
    uint32_t sdstA[4], sdstB[4];
    int arow[4], brow[4];
#pragma unroll
    for (int j = 0; j < 4; j++) {
        const int item = tid + j * 256;
        const int row = item >> 3, ci = item & 7;
        arow[j] = row; brow[j] = row;
        sdstA[j] = row * 128 + ((ci * 16) ^ ((row & 7) << 4));
        sdstB[j] = sdstA[j];
    }

    auto load_chunk = [&](int c, int s) {
        const int r  = c >> 3;
        const int kp = (c & 7) * 64;
        const __nv_bfloat16* Asrc = (r == 1) ? g_alo : g_ahi;
        const __nv_bfloat16* Bsrc = (r == 2) ? g_wtlo : g_wthi;
        const uint32_t aB = smb + s * GSTAGE;
        const uint32_t bB = aB + 16384;
#pragma unroll
        for (int j = 0; j < 4; j++) {
            const int item = tid + j * 256;
            const int ci = item & 7;
            cp16(aB + sdstA[j], Asrc + (size_t)(m0 + arow[j]) * Dn + kp + ci * 8);
        }
#pragma unroll
        for (int j = 0; j < 4; j++) {
            const int item = tid + j * 256;
            const int ci = item & 7;
            cp16(bB + sdstB[j], Bsrc + (size_t)(n0 + brow[j]) * Dn + kp + ci * 8);
        }
    };

    // ldmatrix address components (relative to stage base; k-dependent part XORed in)
    uint32_t aRel[2], aSx[2];
#pragma unroll
    for (int f = 0; f < 2; f++) {
        const int row = wm * 32 + f * 16 + (lane & 15);
        aRel[f] = row * 128;
        aSx[f]  = (row & 7) << 4;
    }
    uint32_t bRel[4], bSx[4];
#pragma unroll
    for (int q = 0; q < 4; q++) {
        const int row = wn * 64 + q * 16 + (lane & 15);
        bRel[q] = row * 128;
        bSx[q]  = (row & 7) << 4;
    }
    const uint32_t halfOff = (lane >> 4) * 16;

    float acc[2][8][4];
#pragma unroll
    for (int i = 0; i < 2; i++)
#pragma unroll
        for (int j = 0; j < 8; j++)
#pragma unroll
            for (int q = 0; q < 4; q++) acc[i][j][q] = 0.f;

    load_chunk(0, 0); CP_COMMIT();
    load_chunk(1, 1); CP_COMMIT();

    for (int i = 0; i < GCHUNKS; i++) {
        const int buf = i & 1;
        if (i == GCHUNKS - 1) { CP_WAIT0(); } else { CP_WAIT1(); }
        __syncthreads();

        const uint32_t aB = smb + buf * GSTAGE;
        const uint32_t bB = aB + 16384;
#pragma unroll
        for (int k16 = 0; k16 < 4; k16++) {
            const uint32_t kb = k16 * 32 + halfOff;
            uint32_t af[2][4];
#pragma unroll
            for (int f = 0; f < 2; f++)
                ldsm4(af[f][0], af[f][1], af[f][2], af[f][3], aB + aRel[f] + (kb ^ aSx[f]));
#pragma unroll
            for (int q = 0; q < 4; q++) {
                uint32_t r0, r1, r2, r3;
                ldsm4(r0, r1, r2, r3, bB + bRel[q] + (kb ^ bSx[q]));
                // n-frag 2q   = {r0, r2} (n rows 0-7 of this 16), 2q+1 = {r1, r3}
#pragma unroll
                for (int f = 0; f < 2; f++) {
                    mma16816(acc[f][2 * q + 0], af[f], r0, r2);
                    mma16816(acc[f][2 * q + 1], af[f], r1, r3);
                }
            }
        }
        __syncthreads();
        if (i + 2 < GCHUNKS) { load_chunk(i + 2, buf); CP_COMMIT(); }
    }

    // epilogue: c frag (m16n8): rows lane/4, lane/4+8; cols (lane%4)*2 + {0,1}
#pragma unroll
    for (int f = 0; f < 2; f++) {
        const int r0 = m0 + wm * 32 + f * 16 + (lane >> 2);
#pragma unroll
        for (int nf = 0; nf < 8; nf++) {
            const int col = n0 + wn * 64 + nf * 8 + (lane & 3) * 2;
            const float2 bv = *(const float2*)(g_bias2 + col);
            float2 o0 = {acc[f][nf][0] + bv.x, acc[f][nf][1] + bv.y};
            float2 o1 = {acc[f][nf][2] + bv.x, acc[f][nf][3] + bv.y};
            *(float2*)(g_xg + (size_t)r0 * NTOT + col)       = o0;
            *(float2*)(g_xg + (size_t)(r0 + 8) * NTOT + col) = o1;
        }
    }
}

// ---------------- Recurrence: persistent, 128 CTAs = 2dir x 8bs x 8hs --------------
// Thread = (column c in [0,128), k-half kh). Wh column held in 128 registers.
// All h reads are warp-uniform smem broadcasts; k-halves reduced through smem.
#define HSTR 260
#define GSTR 132

__global__ void __launch_bounds__(256, 1) recurrence_kernel(const float* __restrict__ Whf,
                                                            const float* __restrict__ Whb,
                                                            float* __restrict__ out) {
    __shared__ float h_sm[8 * HSTR];
    __shared__ float red[128 * 9];
    __shared__ float g_sm[8 * GSTR];
    __shared__ float c_sm[256];
    __shared__ int   len_s[8];

    const int tid = threadIdx.x;
    const int bx  = blockIdx.x;
    const int dir = bx >> 6;
    const int hs  = bx & 7;
    const int bs  = (bx >> 3) & 7;
    const int j0  = hs * 32;
    const int b0  = bs * 8;
    const float* Wh = dir ? Whb : Whf;

    const int kh = tid >> 7;              // k-half
    const int c  = tid & 127;             // local gate column
    const int gate = c >> 5, jj = c & 31;
    const int gcol = gate * Hn + j0 + jj; // global gate column

    // Wh column slice into registers: wreg[k] = Wh[kh*128 + k][gcol]
    float wreg[128];
#pragma unroll
    for (int k = 0; k < 128; k++)
        wreg[k] = __ldg(Wh + (size_t)(kh * 128 + k) * Gn + gcol);

    if (tid < 8) len_s[tid] = g_len[b0 + tid];
    c_sm[tid] = 0.f;
    for (int idx = tid; idx < 8 * HSTR; idx += 256) h_sm[idx] = 0.f;
    __syncthreads();

    const float* xg_dir = g_xg + dir * Gn + gcol;
    unsigned* myflag = &g_flags[dir * 64 + bs * 8 + hs];

    for (int t = 0; t < Tn; t++) {
        if (t > 0) {
            if (tid < 8) {
                const unsigned* fp = &g_flags[dir * 64 + bs * 8 + tid];
                unsigned v;
                do {
                    asm volatile("ld.acquire.gpu.u32 %0, [%1];" : "=r"(v) : "l"(fp) : "memory");
                } while (v < (unsigned)t);
            }
            __syncthreads();
            const float* hg = &g_hbuf[(t - 1) & 1][dir][0];
            for (int i = tid; i < 512; i += 256) {
                const int b = i >> 6;
                const int k4 = i & 63;
                float4 v = __ldcg((const float4*)(hg + (size_t)(b0 + b) * Hn + k4 * 4));
                *(float4*)(h_sm + b * HSTR + k4 * 4) = v;
            }
            __syncthreads();
        }

        // dot: part[b] = sum_k wreg[k] * h[b][kh*128+k]   (h loads warp-uniform)
        float part[8];
#pragma unroll
        for (int b = 0; b < 8; b++) {
            const float* hp = h_sm + b * HSTR + kh * 128;
            float ax = 0.f, ay = 0.f, az = 0.f, aw = 0.f;
#pragma unroll
            for (int k4 = 0; k4 < 32; k4++) {
                const float4 hv = *(const float4*)(hp + k4 * 4);
                ax += wreg[k4 * 4 + 0] * hv.x;
                ay += wreg[k4 * 4 + 1] * hv.y;
                az += wreg[k4 * 4 + 2] * hv.z;
                aw += wreg[k4 * 4 + 3] * hv.w;
            }
            part[b] = (ax + ay) + (az + aw);
        }

        if (kh) {
#pragma unroll
            for (int b = 0; b < 8; b++) red[c * 9 + b] = part[b];
        }
        __syncthreads();
        if (!kh) {
#pragma unroll
            for (int b = 0; b < 8; b++) {
                const int row = dir ? ((Tn - 1 - t + len_s[b]) & (Tn - 1)) : t;
                const float xv = __ldg(xg_dir + ((size_t)(b0 + b) * Tn + row) * NTOT);
                g_sm[b * GSTR + c] = part[b] + red[c * 9 + b] + xv;
            }
        }
        __syncthreads();

        // LSTM cell update: thread -> (b = tid>>5, j = tid&31)
        {
            const int b = tid >> 5, j = tid & 31;
            const float* gp = g_sm + b * GSTR + j;
            const float gi = gp[0], gf = gp[32], gg2 = gp[64], go = gp[96];
            float cc = sigf(gf) * c_sm[tid] + sigf(gi) * tanhf_(gg2);
            c_sm[tid] = cc;
            const float hh = sigf(go) * tanhf_(cc);

            g_hbuf[t & 1][dir][(size_t)(b0 + b) * Hn + j0 + j] = hh;

            const int opos = dir ? ((Tn - 1 - t + len_s[b]) & (Tn - 1)) : t;
            out[((size_t)(b0 + b) * Tn + opos) * (2 * Hn) + dir * Hn + j0 + j] = hh;
        }
        __threadfence();
        __syncthreads();
        if (tid == 0) {
            const unsigned nv = (unsigned)(t + 1);
            asm volatile("st.release.gpu.u32 [%0], %1;" ::"l"(myflag), "r"(nv) : "memory");
        }
    }
}

// ---------------- launch -----------------------------------------------------------
extern "C" void kernel_launch(void* const* d_in, const int* in_sizes, int n_in,
                              void* d_out, int out_size) {
    (void)in_sizes; (void)n_in; (void)out_size;
    const float* inputs   = (const float*)d_in[0];
    const float* pads     = (const float*)d_in[1];
    const float* bn_scale = (const float*)d_in[2];
    const float* bn_bias  = (const float*)d_in[3];
    const float* bn_mean  = (const float*)d_in[4];
    const float* bn_var   = (const float*)d_in[5];
    const float* Wx_f     = (const float*)d_in[6];
    const float* Wh_f     = (const float*)d_in[7];
    const float* b_f      = (const float*)d_in[8];
    const float* Wx_b     = (const float*)d_in[9];
    const float* Wh_b     = (const float*)d_in[10];
    const float* b_b      = (const float*)d_in[11];
    float* out = (float*)d_out;

    static bool inited = false;
    if (!inited) {
        cudaFuncSetAttribute(gemm_mma_kernel,
                             cudaFuncAttributeMaxDynamicSharedMemorySize, GSMEM);
        inited = true;
    }

    init_kernel<<<1, 128>>>();
    lengths_kernel<<<Bn, 256>>>(pads);
    bn_split_kernel<<<Bn * Tn, 128>>>(inputs, pads, bn_scale, bn_bias, bn_mean, bn_var);
    wprep_kernel<<<NTOT, 128>>>(Wx_f, Wx_b, b_f, b_b);
    gemm_mma_kernel<<<dim3(16, 512), 256, GSMEM>>>();
    recurrence_kernel<<<128, 256>>>(Wh_f, Wh_b, out);
}